// round 1
// baseline (speedup 1.0000x reference)
#include <cuda_runtime.h>
#include <cuda_fp16.h>

#define T_STEPS 256
#define NN      64
#define HH      512
#define DT_C    0.01f
#define NBLK    128
#define NTHR    512

// 64 MiB of fp16 transposed weights: layout [n][j][i]
__device__ __half g_Wh[(size_t)NN * HH * HH];
__device__ __half g_Wx[(size_t)NN * HH * HH];
__device__ unsigned g_count = 0;
__device__ unsigned g_gen   = 0;

// ---------------------------------------------------------------------------
// fp32 [n][i][j]  ->  fp16 [n][j][i]   (transpose + convert, tiled)
// ---------------------------------------------------------------------------
__global__ void convert_transpose_kernel(const float* __restrict__ src, int which)
{
    __shared__ float tile[32][33];
    __half* dst = which ? g_Wx : g_Wh;
    const int nmat = blockIdx.z;
    const float* s = src + (size_t)nmat * HH * HH;
    __half*      d = dst + (size_t)nmat * HH * HH;
    const int x0 = blockIdx.x * 32;
    const int y0 = blockIdx.y * 32;
    #pragma unroll
    for (int k = threadIdx.y; k < 32; k += 8)
        tile[k][threadIdx.x] = s[(size_t)(y0 + k) * HH + x0 + threadIdx.x];
    __syncthreads();
    #pragma unroll
    for (int k = threadIdx.y; k < 32; k += 8)
        d[(size_t)(x0 + k) * HH + y0 + threadIdx.x] = __float2half_rn(tile[threadIdx.x][k]);
}

// ---------------------------------------------------------------------------
// states_all[0] = initial_states ; ins_all[0] = x[0]
// ---------------------------------------------------------------------------
__global__ void init_out_kernel(const float* __restrict__ x,
                                const float* __restrict__ init_states,
                                float* __restrict__ states,
                                float* __restrict__ ins)
{
    const int i = blockIdx.x * blockDim.x + threadIdx.x;
    if (i < NN * 2 * HH) states[i] = init_states[i];
    if (i < NN * HH)     ins[i]    = x[i];
}

// ---------------------------------------------------------------------------
// grid-wide barrier (all NBLK blocks co-resident)
// ---------------------------------------------------------------------------
__device__ __forceinline__ void grid_barrier()
{
    __syncthreads();
    if (threadIdx.x == 0) {
        __threadfence();
        const unsigned g = *(volatile unsigned*)&g_gen;
        if (atomicAdd(&g_count, 1u) == NBLK - 1) {
            g_count = 0;
            __threadfence();
            atomicAdd(&g_gen, 1u);
        } else {
            while (*(volatile unsigned*)&g_gen == g) { }
        }
        __threadfence();
    }
    __syncthreads();
}

__device__ __forceinline__ float2 h2f2(unsigned u)
{
    __half2 h = *reinterpret_cast<const __half2*>(&u);
    return __half22float2(h);
}

// ---------------------------------------------------------------------------
// persistent RNN kernel: 128 blocks = 2 per neuron (each handles 256 outputs)
// ---------------------------------------------------------------------------
__global__ void __launch_bounds__(NTHR, 1) rnn_kernel(
    const float* __restrict__ x,      // [T][N][H]
    const float* __restrict__ C,      // [N][N]
    const float* __restrict__ b,      // [N][H]
    float* __restrict__ states,       // [T+1][N][2][H]
    float* __restrict__ ins)          // [T+1][N][H]
{
    const int bid   = blockIdx.x;
    const int n     = bid >> 1;
    const int ibase = (bid & 1) << 8;     // 0 or 256
    const int tid   = threadIdx.x;
    const int warp  = tid >> 5;
    const int lane  = tid & 31;

    __shared__ float sh_C[NN];
    __shared__ float sh_hy[HH];
    __shared__ float sh_ins[HH];
    __shared__ float sh_part[16 * 256];

    if (tid < NN) sh_C[tid] = C[n * NN + tid];
    const float bias = (tid < 256) ? b[n * HH + ibase + tid] : 0.0f;

    // this lane's weight column base: [n][j=warp*32][i = ibase + lane*8]
    const __half* Wh = g_Wh + (size_t)n * HH * HH + (size_t)(warp * 32) * HH + ibase + lane * 8;
    const __half* Wx = g_Wx + (size_t)n * HH * HH + (size_t)(warp * 32) * HH + ibase + lane * 8;

    __syncthreads();

    for (int t = 0; t < T_STEPS; ++t) {
        const float* st = states + (size_t)t * NN * 2 * HH;

        // ---------- phase 1: new_ins[n][j] for all j (thread == j) ----------
        {
            const int j = tid;
            sh_hy[j] = st[(n * 2 + 0) * HH + j];
            float v = 0.0f;
            if (t > 0) {
                float s = 0.0f;
                #pragma unroll 8
                for (int m = 0; m < NN; ++m)
                    s += sh_C[m] * st[(m * 2) * HH + j];    // hy of neuron m
                v = s * x[((size_t)t * NN + n) * HH + j];
            }
            sh_ins[j] = v;
            if ((bid & 1) == 0)
                ins[((size_t)(t + 1) * NN + n) * HH + j] = v;
        }
        __syncthreads();

        // ---------- phase 2: pre = Wh.hy + Wx.ins (fp16 weights, fp32 acc) --
        float acc[8];
        #pragma unroll
        for (int k = 0; k < 8; ++k) acc[k] = 0.0f;

        #pragma unroll 4
        for (int jj = 0; jj < 32; ++jj) {
            const float hyj = sh_hy[warp * 32 + jj];
            const float inj = sh_ins[warp * 32 + jj];
            const uint4 a = *reinterpret_cast<const uint4*>(Wh + (size_t)jj * HH);
            const uint4 c = *reinterpret_cast<const uint4*>(Wx + (size_t)jj * HH);
            float2 f;
            f = h2f2(a.x); acc[0] += f.x * hyj; acc[1] += f.y * hyj;
            f = h2f2(a.y); acc[2] += f.x * hyj; acc[3] += f.y * hyj;
            f = h2f2(a.z); acc[4] += f.x * hyj; acc[5] += f.y * hyj;
            f = h2f2(a.w); acc[6] += f.x * hyj; acc[7] += f.y * hyj;
            f = h2f2(c.x); acc[0] += f.x * inj; acc[1] += f.y * inj;
            f = h2f2(c.y); acc[2] += f.x * inj; acc[3] += f.y * inj;
            f = h2f2(c.z); acc[4] += f.x * inj; acc[5] += f.y * inj;
            f = h2f2(c.w); acc[6] += f.x * inj; acc[7] += f.y * inj;
        }

        {
            float* pp = sh_part + warp * 256 + lane * 8;
            #pragma unroll
            for (int k = 0; k < 8; ++k) pp[k] = acc[k];
        }
        __syncthreads();

        // ---------- reduce 16 warp-partials + state update (thread == i) ----
        if (tid < 256) {
            float s = bias;
            #pragma unroll
            for (int w2 = 0; w2 < 16; ++w2) s += sh_part[w2 * 256 + tid];
            const int i  = ibase + tid;
            const float hy = sh_hy[i];
            const float hz = st[(n * 2 + 1) * HH + i];
            const float hz_n = hz + DT_C * (tanhf(s) - hy - hz);   // GAMMA=EPS=1
            const float hy_n = hy + DT_C * hz_n;
            float* stn = states + (size_t)(t + 1) * NN * 2 * HH;
            stn[(n * 2 + 0) * HH + i] = hy_n;
            stn[(n * 2 + 1) * HH + i] = hz_n;
        }

        grid_barrier();
    }
}

// ---------------------------------------------------------------------------
extern "C" void kernel_launch(void* const* d_in, const int* in_sizes, int n_in,
                              void* d_out, int out_size)
{
    const float* x   = (const float*)d_in[0];   // (256, 64, 512)
    const float* C   = (const float*)d_in[1];   // (64, 64)
    const float* Wh  = (const float*)d_in[2];   // (64, 512, 512)
    const float* Wx  = (const float*)d_in[3];   // (64, 512, 512)
    const float* b   = (const float*)d_in[4];   // (64, 512)
    const float* s0  = (const float*)d_in[5];   // (64, 2, 512)

    float* out    = (float*)d_out;
    float* states = out;                                          // (257,64,2,512)
    float* ins    = out + (size_t)(T_STEPS + 1) * NN * 2 * HH;    // (257,64,512)

    dim3 tb(32, 8, 1), tg(16, 16, NN);
    convert_transpose_kernel<<<tg, tb>>>(Wh, 0);
    convert_transpose_kernel<<<tg, tb>>>(Wx, 1);
    init_out_kernel<<<(NN * 2 * HH + 255) / 256, 256>>>(x, s0, states, ins);
    rnn_kernel<<<NBLK, NTHR>>>(x, C, b, states, ins);
}

// round 2
// speedup vs baseline: 1.0605x; 1.0605x over previous
#include <cuda_runtime.h>
#include <cuda_fp16.h>

#define T_STEPS 256
#define NN      64
#define HH      512
#define DT_C    0.01f
#define NBLK    256
#define NTHR    256
#define RES_IT  12                                  // resident j-iters (of 32) per warp
#define DYN_SMEM (8 * RES_IT * 2 * 512)             // 98304 B per block

// 64 MiB of fp16 transposed weights: layout [n][j][i]
__device__ __half g_Wh[(size_t)NN * HH * HH];
__device__ __half g_Wx[(size_t)NN * HH * HH];
__device__ unsigned g_count;
__device__ unsigned g_gen;
__device__ unsigned g_ins_cnt[NN];

// ---------------------------------------------------------------------------
// fp32 [n][i][j]  ->  fp16 [n][j][i]   (transpose + convert, tiled)
// ---------------------------------------------------------------------------
__global__ void convert_transpose_kernel(const float* __restrict__ src, int which)
{
    __shared__ float tile[32][33];
    __half* dst = which ? g_Wx : g_Wh;
    const int nmat = blockIdx.z;
    const float* s = src + (size_t)nmat * HH * HH;
    __half*      d = dst + (size_t)nmat * HH * HH;
    const int x0 = blockIdx.x * 32;
    const int y0 = blockIdx.y * 32;
    #pragma unroll
    for (int k = threadIdx.y; k < 32; k += 8)
        tile[k][threadIdx.x] = s[(size_t)(y0 + k) * HH + x0 + threadIdx.x];
    __syncthreads();
    #pragma unroll
    for (int k = threadIdx.y; k < 32; k += 8)
        d[(size_t)(x0 + k) * HH + y0 + threadIdx.x] = __float2half_rn(tile[threadIdx.x][k]);
}

// ---------------------------------------------------------------------------
// states_all[0] = initial_states ; ins_all[0] = x[0] ; reset sync counters
// ---------------------------------------------------------------------------
__global__ void init_out_kernel(const float* __restrict__ x,
                                const float* __restrict__ init_states,
                                float* __restrict__ states,
                                float* __restrict__ ins)
{
    const int i = blockIdx.x * blockDim.x + threadIdx.x;
    if (i < NN * 2 * HH) states[i] = init_states[i];
    if (i < NN * HH)     ins[i]    = x[i];
    if (i < NN)          g_ins_cnt[i] = 0;
    if (i == 0)          { g_count = 0; g_gen = 0; }
}

// ---------------------------------------------------------------------------
__device__ __forceinline__ void grid_barrier()
{
    __syncthreads();
    if (threadIdx.x == 0) {
        __threadfence();
        const unsigned g = *(volatile unsigned*)&g_gen;
        if (atomicAdd(&g_count, 1u) == NBLK - 1) {
            g_count = 0;
            __threadfence();
            atomicAdd(&g_gen, 1u);
        } else {
            while (*(volatile unsigned*)&g_gen == g) __nanosleep(32);
        }
        __threadfence();
    }
    __syncthreads();
}

__device__ __forceinline__ void fma8(float* acc, uint4 a, float v)
{
    float2 f;
    f = __half22float2(*reinterpret_cast<__half2*>(&a.x)); acc[0] += f.x * v; acc[1] += f.y * v;
    f = __half22float2(*reinterpret_cast<__half2*>(&a.y)); acc[2] += f.x * v; acc[3] += f.y * v;
    f = __half22float2(*reinterpret_cast<__half2*>(&a.z)); acc[4] += f.x * v; acc[5] += f.y * v;
    f = __half22float2(*reinterpret_cast<__half2*>(&a.w)); acc[6] += f.x * v; acc[7] += f.y * v;
}

// ---------------------------------------------------------------------------
// persistent RNN: 256 blocks = 4 per neuron (each 128 outputs), 2 blocks/SM
// ---------------------------------------------------------------------------
__global__ void __launch_bounds__(NTHR, 2) rnn_kernel(
    const float* __restrict__ x,      // [T][N][H]
    const float* __restrict__ C,      // [N][N]
    const float* __restrict__ b,      // [N][H]
    float* __restrict__ states,       // [T+1][N][2][H]
    float* __restrict__ ins)          // [T+1][N][H]
{
    extern __shared__ __align__(16) unsigned char dynsmem[];
    uint4* sres = reinterpret_cast<uint4*>(dynsmem);

    __shared__ float sh_hy[HH];
    __shared__ float sh_ins[HH];
    __shared__ float sh_C[NN];
    __shared__ float sh_cm[2 * 128];
    __shared__ float sh_part[8 * 128];

    const int bid   = blockIdx.x;
    const int n     = bid >> 2;
    const int ibase = (bid & 3) * 128;
    const int tid   = threadIdx.x;
    const int warp  = tid >> 5;
    const int lane  = tid & 31;
    const int hw    = lane >> 4;      // row parity within iter
    const int li    = lane & 15;      // i-chunk (8 halves via uint4)
    const int wbase = warp * 64;      // warp's j-range start

    if (tid < NN) sh_C[tid] = C[n * NN + tid];
    const float bias = (tid < 128) ? b[n * HH + ibase + tid] : 0.0f;

    const __half* pWh = g_Wh + (size_t)n * HH * HH + (size_t)(wbase + hw) * HH + ibase + li * 8;
    const __half* pWx = g_Wx + (size_t)n * HH * HH + (size_t)(wbase + hw) * HH + ibase + li * 8;

    // ---- stage resident weights into shared (once) ----
    for (int it = 0; it < RES_IT; ++it) {
        sres[((warp * RES_IT + it) * 2 + 0) * 32 + hw * 16 + li] =
            *reinterpret_cast<const uint4*>(pWh + (size_t)it * 2 * HH);
        sres[((warp * RES_IT + it) * 2 + 1) * 32 + hw * 16 + li] =
            *reinterpret_cast<const uint4*>(pWx + (size_t)it * 2 * HH);
    }
    __syncthreads();

    for (int t = 0; t < T_STEPS; ++t) {
        const float* st = states + (size_t)t * NN * 2 * HH;

        // own neuron's hy into shared (float2 per thread)
        reinterpret_cast<float2*>(sh_hy)[tid] =
            reinterpret_cast<const float2*>(st + n * 2 * HH)[tid];

        float xv = 0.0f, hzv = 0.0f;
        if (tid < 128) {
            hzv = st[(n * 2 + 1) * HH + ibase + tid];
            if (t > 0) xv = x[((size_t)t * NN + n) * HH + ibase + tid];
        }

        // ---- distributed C-mix: this block computes ins for its 128 j's ----
        const int jloc = tid & 127;
        float cm = 0.0f;
        if (t > 0) {
            const int mb = (tid < 128) ? 0 : 32;
            const float* sp = st + (size_t)(2 * mb) * HH + ibase + jloc;
            #pragma unroll 8
            for (int m = 0; m < 32; ++m)
                cm += sh_C[mb + m] * sp[(size_t)m * 2 * HH];
        }
        sh_cm[tid] = cm;
        __syncthreads();

        if (tid < 128) {
            const float v = (t > 0) ? (sh_cm[tid] + sh_cm[tid + 128]) * xv : 0.0f;
            ins[((size_t)(t + 1) * NN + n) * HH + ibase + tid] = v;
            __threadfence();
        }
        __syncthreads();
        if (tid == 0) atomicAdd(&g_ins_cnt[n], 1u);

        // ---- W_h . hy  (hides sibling ins latency) ----
        float acc[8];
        #pragma unroll
        for (int k = 0; k < 8; ++k) acc[k] = 0.0f;

        #pragma unroll
        for (int it = 0; it < RES_IT; ++it) {
            const float v = sh_hy[wbase + 2 * it + hw];
            fma8(acc, sres[((warp * RES_IT + it) * 2 + 0) * 32 + hw * 16 + li], v);
        }
        #pragma unroll 5
        for (int it = RES_IT; it < 32; ++it) {
            const float v = sh_hy[wbase + 2 * it + hw];
            fma8(acc, *reinterpret_cast<const uint4*>(pWh + (size_t)it * 2 * HH), v);
        }

        // ---- wait for all 4 sibling blocks' ins chunks, gather full 512 ----
        if (tid == 0) {
            const unsigned target = 4u * (unsigned)(t + 1);
            while (*(volatile unsigned*)&g_ins_cnt[n] < target) __nanosleep(32);
            __threadfence();
        }
        __syncthreads();
        reinterpret_cast<float2*>(sh_ins)[tid] =
            reinterpret_cast<const float2*>(ins + ((size_t)(t + 1) * NN + n) * HH)[tid];
        __syncthreads();

        // ---- W_x . ins ----
        #pragma unroll
        for (int it = 0; it < RES_IT; ++it) {
            const float v = sh_ins[wbase + 2 * it + hw];
            fma8(acc, sres[((warp * RES_IT + it) * 2 + 1) * 32 + hw * 16 + li], v);
        }
        #pragma unroll 5
        for (int it = RES_IT; it < 32; ++it) {
            const float v = sh_ins[wbase + 2 * it + hw];
            fma8(acc, *reinterpret_cast<const uint4*>(pWx + (size_t)it * 2 * HH), v);
        }

        // ---- reduce: half-warp pair, then 8 warps via shared ----
        #pragma unroll
        for (int k = 0; k < 8; ++k)
            acc[k] += __shfl_down_sync(0xffffffffu, acc[k], 16);
        if (hw == 0) {
            #pragma unroll
            for (int k = 0; k < 8; ++k)
                sh_part[warp * 128 + li * 8 + k] = acc[k];
        }
        __syncthreads();

        if (tid < 128) {
            float s = bias;
            #pragma unroll
            for (int w2 = 0; w2 < 8; ++w2) s += sh_part[w2 * 128 + tid];
            const float hy  = sh_hy[ibase + tid];
            const float hz_n = hzv + DT_C * (tanhf(s) - hy - hzv);   // GAMMA=EPS=1
            const float hy_n = hy + DT_C * hz_n;
            float* stn = states + (size_t)(t + 1) * NN * 2 * HH;
            stn[(n * 2 + 0) * HH + ibase + tid] = hy_n;
            stn[(n * 2 + 1) * HH + ibase + tid] = hz_n;
        }

        grid_barrier();
    }
}

// ---------------------------------------------------------------------------
extern "C" void kernel_launch(void* const* d_in, const int* in_sizes, int n_in,
                              void* d_out, int out_size)
{
    const float* x   = (const float*)d_in[0];   // (256, 64, 512)
    const float* C   = (const float*)d_in[1];   // (64, 64)
    const float* Wh  = (const float*)d_in[2];   // (64, 512, 512)
    const float* Wx  = (const float*)d_in[3];   // (64, 512, 512)
    const float* b   = (const float*)d_in[4];   // (64, 512)
    const float* s0  = (const float*)d_in[5];   // (64, 2, 512)

    float* out    = (float*)d_out;
    float* states = out;                                          // (257,64,2,512)
    float* ins    = out + (size_t)(T_STEPS + 1) * NN * 2 * HH;    // (257,64,512)

    cudaFuncSetAttribute(rnn_kernel, cudaFuncAttributeMaxDynamicSharedMemorySize, DYN_SMEM);

    dim3 tb(32, 8, 1), tg(16, 16, NN);
    convert_transpose_kernel<<<tg, tb>>>(Wh, 0);
    convert_transpose_kernel<<<tg, tb>>>(Wx, 1);
    init_out_kernel<<<(NN * 2 * HH + 255) / 256, 256>>>(x, s0, states, ins);
    rnn_kernel<<<NBLK, NTHR, DYN_SMEM>>>(x, C, b, states, ins);
}

// round 3
// speedup vs baseline: 1.3240x; 1.2485x over previous
#include <cuda_runtime.h>
#include <cuda_fp16.h>

#define T_STEPS 256
#define NN      64
#define HH      512
#define DT_C    0.01f
#define NBLK    256
#define NTHR    256
#define RES_IT  12                                  // shared-resident j-iters (of 32) per warp
#define DYN_SMEM (8 * RES_IT * 2 * 512)             // 98304 B per block

// 64 MiB of fp16 transposed weights: layout [n][j][i]
__device__ __half g_Wh[(size_t)NN * HH * HH];
__device__ __half g_Wx[(size_t)NN * HH * HH];
__device__ unsigned g_state_cnt;        // +1 per block per step (monotonic)
__device__ unsigned g_hy_cnt[NN];       // +1 per sibling per step
__device__ unsigned g_ins_cnt[NN];      // +1 per sibling per step

// ---------------------------------------------------------------------------
__device__ __forceinline__ void arrive_rel(unsigned* ctr)
{
    asm volatile("red.release.gpu.add.u32 [%0], 1;" :: "l"(ctr) : "memory");
}
__device__ __forceinline__ unsigned ld_acq(unsigned* ctr)
{
    unsigned v;
    asm volatile("ld.acquire.gpu.u32 %0, [%1];" : "=r"(v) : "l"(ctr) : "memory");
    return v;
}
__device__ __forceinline__ void spin_until(unsigned* ctr, unsigned target)
{
    if (ld_acq(ctr) >= target) return;
    while (ld_acq(ctr) < target) __nanosleep(20);
}

// ---------------------------------------------------------------------------
// fp32 [n][i][j]  ->  fp16 [n][j][i]   (transpose + convert, tiled)
// ---------------------------------------------------------------------------
__global__ void convert_transpose_kernel(const float* __restrict__ src, int which)
{
    __shared__ float tile[32][33];
    __half* dst = which ? g_Wx : g_Wh;
    const int nmat = blockIdx.z;
    const float* s = src + (size_t)nmat * HH * HH;
    __half*      d = dst + (size_t)nmat * HH * HH;
    const int x0 = blockIdx.x * 32;
    const int y0 = blockIdx.y * 32;
    #pragma unroll
    for (int k = threadIdx.y; k < 32; k += 8)
        tile[k][threadIdx.x] = s[(size_t)(y0 + k) * HH + x0 + threadIdx.x];
    __syncthreads();
    #pragma unroll
    for (int k = threadIdx.y; k < 32; k += 8)
        d[(size_t)(x0 + k) * HH + y0 + threadIdx.x] = __float2half_rn(tile[threadIdx.x][k]);
}

// ---------------------------------------------------------------------------
__global__ void init_out_kernel(const float* __restrict__ x,
                                const float* __restrict__ init_states,
                                float* __restrict__ states,
                                float* __restrict__ ins)
{
    const int i = blockIdx.x * blockDim.x + threadIdx.x;
    if (i < NN * 2 * HH) states[i] = init_states[i];
    if (i < NN * HH)     ins[i]    = x[i];
    if (i < NN)          { g_hy_cnt[i] = 0; g_ins_cnt[i] = 0; }
    if (i == 0)          g_state_cnt = 0;
}

// ---------------------------------------------------------------------------
__device__ __forceinline__ void fma8(float* acc, uint4 a, float v)
{
    float2 f;
    f = __half22float2(*reinterpret_cast<__half2*>(&a.x)); acc[0] += f.x * v; acc[1] += f.y * v;
    f = __half22float2(*reinterpret_cast<__half2*>(&a.y)); acc[2] += f.x * v; acc[3] += f.y * v;
    f = __half22float2(*reinterpret_cast<__half2*>(&a.z)); acc[4] += f.x * v; acc[5] += f.y * v;
    f = __half22float2(*reinterpret_cast<__half2*>(&a.w)); acc[6] += f.x * v; acc[7] += f.y * v;
}

// ---------------------------------------------------------------------------
// persistent RNN: 256 blocks = 4 per neuron (each 128 outputs), 2 blocks/SM.
// No blocking grid barrier: monotonic acquire/release counters, every wait
// hidden behind independent GEMV work.
// ---------------------------------------------------------------------------
__global__ void __launch_bounds__(NTHR, 2) rnn_kernel(
    const float* __restrict__ x,      // [T][N][H]
    const float* __restrict__ C,      // [N][N]
    const float* __restrict__ b,      // [N][H]
    float* __restrict__ states,       // [T+1][N][2][H]
    float* __restrict__ ins)          // [T+1][N][H]
{
    extern __shared__ __align__(16) unsigned char dynsmem[];
    uint4* sres = reinterpret_cast<uint4*>(dynsmem);

    __shared__ float sh_hy[HH];
    __shared__ float sh_ins[HH];
    __shared__ float sh_C[NN];
    __shared__ float sh_cm[2 * 128];
    __shared__ float sh_part[8 * 128];

    const int bid   = blockIdx.x;
    const int n     = bid >> 2;
    const int ibase = (bid & 3) * 128;
    const int tid   = threadIdx.x;
    const int warp  = tid >> 5;
    const int lane  = tid & 31;
    const int hw    = lane >> 4;      // row parity within iter
    const int li    = lane & 15;      // i-chunk (8 halves via uint4)
    const int wbase = warp * 64;      // warp's j-range start

    if (tid < NN) sh_C[tid] = C[n * NN + tid];
    const float bias = (tid < 128) ? b[n * HH + ibase + tid] : 0.0f;

    const __half* pWh = g_Wh + (size_t)n * HH * HH + (size_t)(wbase + hw) * HH + ibase + li * 8;
    const __half* pWx = g_Wx + (size_t)n * HH * HH + (size_t)(wbase + hw) * HH + ibase + li * 8;

    // ---- stage resident weights into shared (once) ----
    for (int it = 0; it < RES_IT; ++it) {
        sres[((warp * RES_IT + it) * 2 + 0) * 32 + hw * 16 + li] =
            *reinterpret_cast<const uint4*>(pWh + (size_t)it * 2 * HH);
        sres[((warp * RES_IT + it) * 2 + 1) * 32 + hw * 16 + li] =
            *reinterpret_cast<const uint4*>(pWx + (size_t)it * 2 * HH);
    }

    // hz for own 128 outputs lives in a register across all steps
    float hz_r = (tid < 128) ? states[(n * 2 + 1) * HH + ibase + tid] : 0.0f;

    __syncthreads();

    for (int t = 0; t < T_STEPS; ++t) {
        const float* st  = states + (size_t)t * NN * 2 * HH;
        float*       stn = states + (size_t)(t + 1) * NN * 2 * HH;

        // ---- wait siblings' hy(t) chunks (cheap: 4 arrivals, usually done) --
        if (t > 0) {
            if (tid == 0) spin_until(&g_hy_cnt[n], 4u * (unsigned)t);
            __syncthreads();
        }
        reinterpret_cast<float2*>(sh_hy)[tid] =
            reinterpret_cast<const float2*>(st + n * 2 * HH)[tid];
        const float xv = (tid < 128) ? x[((size_t)t * NN + n) * HH + ibase + tid] : 0.0f;
        __syncthreads();

        float acc[8];
        #pragma unroll
        for (int k = 0; k < 8; ++k) acc[k] = 0.0f;

        // ---- Wh.hy global-resident iters: hides the global state wait ------
        #pragma unroll 5
        for (int it = RES_IT; it < 32; ++it) {
            const float v = sh_hy[wbase + 2 * it + hw];
            fma8(acc, *reinterpret_cast<const uint4*>(pWh + (size_t)it * 2 * HH), v);
        }

        // ---- global wait: all 256 blocks finished step t-1 ------------------
        if (t > 0) {
            if (tid == 0) spin_until(&g_state_cnt, 256u * (unsigned)t);
            __syncthreads();
        }

        // ---- distributed C-mix: ins chunk for own 128 j's ------------------
        {
            const int jloc = tid & 127;
            float cm = 0.0f;
            if (t > 0) {
                const int mb = (tid < 128) ? 0 : 32;
                const float* sp = st + (size_t)(2 * mb) * HH + ibase + jloc;
                #pragma unroll 8
                for (int m = 0; m < 32; ++m)
                    cm += sh_C[mb + m] * sp[(size_t)m * 2 * HH];
            }
            sh_cm[tid] = cm;
        }
        __syncthreads();
        if (tid < 128) {
            const float v = (t > 0) ? (sh_cm[tid] + sh_cm[tid + 128]) * xv : 0.0f;
            ins[((size_t)(t + 1) * NN + n) * HH + ibase + tid] = v;
        }
        __syncthreads();
        if (tid == 0) arrive_rel(&g_ins_cnt[n]);

        // ---- Wh.hy shared-resident iters: hides the sibling ins wait -------
        #pragma unroll
        for (int it = 0; it < RES_IT; ++it) {
            const float v = sh_hy[wbase + 2 * it + hw];
            fma8(acc, sres[((warp * RES_IT + it) * 2 + 0) * 32 + hw * 16 + li], v);
        }

        // ---- gather full ins(t+1) ------------------------------------------
        if (tid == 0) spin_until(&g_ins_cnt[n], 4u * (unsigned)(t + 1));
        __syncthreads();
        reinterpret_cast<float2*>(sh_ins)[tid] =
            reinterpret_cast<const float2*>(ins + ((size_t)(t + 1) * NN + n) * HH)[tid];
        __syncthreads();

        // ---- Wx.ins --------------------------------------------------------
        #pragma unroll
        for (int it = 0; it < RES_IT; ++it) {
            const float v = sh_ins[wbase + 2 * it + hw];
            fma8(acc, sres[((warp * RES_IT + it) * 2 + 1) * 32 + hw * 16 + li], v);
        }
        #pragma unroll 5
        for (int it = RES_IT; it < 32; ++it) {
            const float v = sh_ins[wbase + 2 * it + hw];
            fma8(acc, *reinterpret_cast<const uint4*>(pWx + (size_t)it * 2 * HH), v);
        }

        // ---- reduce: half-warp pair, then 8 warps via shared ----------------
        #pragma unroll
        for (int k = 0; k < 8; ++k)
            acc[k] += __shfl_down_sync(0xffffffffu, acc[k], 16);
        if (hw == 0) {
            #pragma unroll
            for (int k = 0; k < 8; ++k)
                sh_part[warp * 128 + li * 8 + k] = acc[k];
        }
        __syncthreads();

        // ---- state update (hz carried in registers) ------------------------
        if (tid < 128) {
            float s = bias;
            #pragma unroll
            for (int w2 = 0; w2 < 8; ++w2) s += sh_part[w2 * 128 + tid];
            const float hy   = sh_hy[ibase + tid];
            const float hz_n = hz_r + DT_C * (tanhf(s) - hy - hz_r);   // GAMMA=EPS=1
            const float hy_n = hy + DT_C * hz_n;
            hz_r = hz_n;
            stn[(n * 2 + 0) * HH + ibase + tid] = hy_n;
            stn[(n * 2 + 1) * HH + ibase + tid] = hz_n;
        }
        __syncthreads();
        if (tid == 0) {
            arrive_rel(&g_hy_cnt[n]);      // siblings may start next Wh.hy
            arrive_rel(&g_state_cnt);      // everyone may start next C-mix
        }
    }
}

// ---------------------------------------------------------------------------
extern "C" void kernel_launch(void* const* d_in, const int* in_sizes, int n_in,
                              void* d_out, int out_size)
{
    const float* x   = (const float*)d_in[0];   // (256, 64, 512)
    const float* C   = (const float*)d_in[1];   // (64, 64)
    const float* Wh  = (const float*)d_in[2];   // (64, 512, 512)
    const float* Wx  = (const float*)d_in[3];   // (64, 512, 512)
    const float* b   = (const float*)d_in[4];   // (64, 512)
    const float* s0  = (const float*)d_in[5];   // (64, 2, 512)

    float* out    = (float*)d_out;
    float* states = out;                                          // (257,64,2,512)
    float* ins    = out + (size_t)(T_STEPS + 1) * NN * 2 * HH;    // (257,64,512)

    cudaFuncSetAttribute(rnn_kernel, cudaFuncAttributeMaxDynamicSharedMemorySize, DYN_SMEM);

    dim3 tb(32, 8, 1), tg(16, 16, NN);
    convert_transpose_kernel<<<tg, tb>>>(Wh, 0);
    convert_transpose_kernel<<<tg, tb>>>(Wx, 1);
    init_out_kernel<<<(NN * 2 * HH + 255) / 256, 256>>>(x, s0, states, ins);
    rnn_kernel<<<NBLK, NTHR, DYN_SMEM>>>(x, C, b, states, ins);
}